// round 10
// baseline (speedup 1.0000x reference)
#include <cuda_runtime.h>
#include <cstdint>

// LatentTexture: quantize-then-bilinear-sample two latent textures.
//   hi: 12 ch, 2048x2048, 8-bit quant (qmax=255)
//   lo:  4 ch,  512x512,  4-bit quant (qmax=15)
// out[b,0:12]=hi, out[b,12:16]=lo. fp32.
//
// R9 analysis: sorted gather is AT the DRAM traffic floor (~190 MB with 128B
// granules). This round minimizes sort-pass overhead:
//   - hist stores per-sample Morton keys (u16) for scatter to reuse
//   - warp-shuffle scan (3 barriers instead of 20)
//   - 4 samples/thread everywhere for atomic MLP

#define NSAMP 131072
#define BLK 256
#define NBINS 16384          // 128x128 tiles of 16x16 hi texels
#define SCAN_T 1024
#define BINS_PER_T (NBINS / SCAN_T)   // 16

__device__ int            g_hist[NBINS];     // zero at load; scan re-zeroes
__device__ int            g_cursor[NBINS];
__device__ unsigned short g_key[NSAMP];
__device__ float4         g_sorted[NSAMP];   // (u, v, idx_bits, pad)

// ---------------------------------------------------------------- helpers
__device__ __forceinline__ float qlevel(float x, float qmax) {
    float xc = fminf(fmaxf(x, 0.0f), 1.0f);
    return rintf(__fmul_rn(xc, qmax));
}

__device__ __forceinline__ uint32_t spread8(uint32_t x) {
    x &= 0xFFu;
    x = (x | (x << 4)) & 0x0F0Fu;
    x = (x | (x << 2)) & 0x3333u;
    x = (x | (x << 1)) & 0x5555u;
    return x;
}

__device__ __forceinline__ int sample_key(float u, float v) {
    float gx = __fadd_rn(__fmul_rn(u, 2.0f), -1.0f);
    float gy = __fadd_rn(__fmul_rn(v, 2.0f), -1.0f);
    float ix = __fmul_rn(__fmul_rn(__fadd_rn(gx, 1.0f), 0.5f), 2047.0f);
    float iy = __fmul_rn(__fmul_rn(__fadd_rn(gy, 1.0f), 0.5f), 2047.0f);
    int tx = min(max((int)floorf(ix), 0), 2047) >> 4;   // 0..127
    int ty = min(max((int)floorf(iy), 0), 2047) >> 4;   // 0..127
    return (int)((spread8((uint32_t)ty) << 1) | spread8((uint32_t)tx));
}

// ---------------------------------------------------------------- sort
__global__ void __launch_bounds__(BLK)
hist_kernel(const float* __restrict__ uv) {
    int t = blockIdx.x * BLK + threadIdx.x;          // t in [0, NSAMP/4)
    const float4* uv4 = reinterpret_cast<const float4*>(uv);
    float4 a = __ldg(uv4 + 2 * t);
    float4 b = __ldg(uv4 + 2 * t + 1);

    int k0 = sample_key(a.x, a.y);
    int k1 = sample_key(a.z, a.w);
    int k2 = sample_key(b.x, b.y);
    int k3 = sample_key(b.z, b.w);

    atomicAdd(&g_hist[k0], 1);   // results unused -> RED (no return)
    atomicAdd(&g_hist[k1], 1);
    atomicAdd(&g_hist[k2], 1);
    atomicAdd(&g_hist[k3], 1);

    ushort4 ks;
    ks.x = (unsigned short)k0;
    ks.y = (unsigned short)k1;
    ks.z = (unsigned short)k2;
    ks.w = (unsigned short)k3;
    reinterpret_cast<ushort4*>(g_key)[t] = ks;       // STG.64 coalesced
}

__global__ void __launch_bounds__(SCAN_T) scan_kernel() {
    __shared__ int warp_sum[32];
    int tid = threadIdx.x;
    int lane = tid & 31;
    int wid = tid >> 5;

    int loc[BINS_PER_T];
    int tot = 0;
#pragma unroll
    for (int k = 0; k < BINS_PER_T / 4; ++k) {
        int4 v = reinterpret_cast<const int4*>(g_hist)[tid * (BINS_PER_T / 4) + k];
        loc[4 * k + 0] = v.x; loc[4 * k + 1] = v.y;
        loc[4 * k + 2] = v.z; loc[4 * k + 3] = v.w;
        tot += v.x + v.y + v.z + v.w;
    }

    // warp inclusive scan of per-thread totals
    int inc = tot;
#pragma unroll
    for (int d = 1; d < 32; d <<= 1) {
        int v = __shfl_up_sync(0xffffffffu, inc, d);
        if (lane >= d) inc += v;
    }
    if (lane == 31) warp_sum[wid] = inc;
    __syncthreads();

    if (wid == 0) {
        int ws = warp_sum[lane];
        int wi = ws;
#pragma unroll
        for (int d = 1; d < 32; d <<= 1) {
            int v = __shfl_up_sync(0xffffffffu, wi, d);
            if (lane >= d) wi += v;
        }
        warp_sum[lane] = wi - ws;   // exclusive warp offsets
    }
    __syncthreads();

    int run = warp_sum[wid] + inc - tot;   // exclusive offset for this thread
#pragma unroll
    for (int k = 0; k < BINS_PER_T / 4; ++k) {
        int4 c;
        c.x = run;              run += loc[4 * k + 0];
        c.y = run;              run += loc[4 * k + 1];
        c.z = run;              run += loc[4 * k + 2];
        c.w = run;              run += loc[4 * k + 3];
        reinterpret_cast<int4*>(g_cursor)[tid * (BINS_PER_T / 4) + k] = c;
        // re-zero hist for the next graph replay
        reinterpret_cast<int4*>(g_hist)[tid * (BINS_PER_T / 4) + k] =
            make_int4(0, 0, 0, 0);
    }
}

__global__ void __launch_bounds__(BLK)
scatter_kernel(const float* __restrict__ uv) {
    int t = blockIdx.x * BLK + threadIdx.x;          // t in [0, NSAMP/4)
    const float4* uv4 = reinterpret_cast<const float4*>(uv);
    float4 a = __ldg(uv4 + 2 * t);
    float4 b = __ldg(uv4 + 2 * t + 1);
    ushort4 ks = reinterpret_cast<const ushort4*>(g_key)[t];

    int pos0 = atomicAdd(&g_cursor[ks.x], 1);        // 4 independent 318-cyc
    int pos1 = atomicAdd(&g_cursor[ks.y], 1);
    int pos2 = atomicAdd(&g_cursor[ks.z], 1);
    int pos3 = atomicAdd(&g_cursor[ks.w], 1);

    int base = 4 * t;
    g_sorted[pos0] = make_float4(a.x, a.y, __int_as_float(base + 0), 0.0f);
    g_sorted[pos1] = make_float4(a.z, a.w, __int_as_float(base + 1), 0.0f);
    g_sorted[pos2] = make_float4(b.x, b.y, __int_as_float(base + 2), 0.0f);
    g_sorted[pos3] = make_float4(b.z, b.w, __int_as_float(base + 3), 0.0f);
}

// ---------------------------------------------------------------- gather
template <int HW>
__device__ __forceinline__ void sample4(const float* __restrict__ tex,
                                        float u, float v,
                                        float qmax, float invq,
                                        float* __restrict__ res) {
    float gx = __fadd_rn(__fmul_rn(u, 2.0f), -1.0f);
    float gy = __fadd_rn(__fmul_rn(v, 2.0f), -1.0f);
    float ix = __fmul_rn(__fmul_rn(__fadd_rn(gx, 1.0f), 0.5f), (float)(HW - 1));
    float iy = __fmul_rn(__fmul_rn(__fadd_rn(gy, 1.0f), 0.5f), (float)(HW - 1));

    float ix0f = floorf(ix);
    float iy0f = floorf(iy);
    float wx = __fadd_rn(ix, -ix0f);
    float wy = __fadd_rn(iy, -iy0f);

    int ix0 = min(max((int)ix0f, 0), HW - 1);
    int iy0 = min(max((int)iy0f, 0), HW - 1);
    int ix1 = min(ix0 + 1, HW - 1);
    int iy1 = min(iy0 + 1, HW - 1);

    float w00 = (1.0f - wy) * (1.0f - wx);
    float w01 = (1.0f - wy) * wx;
    float w10 = wy * (1.0f - wx);
    float w11 = wy * wx;

    size_t r0 = (size_t)iy0 * HW;
    size_t r1 = (size_t)iy1 * HW;
    size_t o00 = r0 + ix0, o01 = r0 + ix1;
    size_t o10 = r1 + ix0, o11 = r1 + ix1;

    const size_t plane = (size_t)HW * HW;

    float t00[4], t01[4], t10[4], t11[4];
#pragma unroll
    for (int c = 0; c < 4; ++c) {
        const float* p = tex + (size_t)c * plane;
        t00[c] = __ldg(p + o00);
        t01[c] = __ldg(p + o01);
        t10[c] = __ldg(p + o10);
        t11[c] = __ldg(p + o11);
    }
#pragma unroll
    for (int c = 0; c < 4; ++c) {
        float acc = qlevel(t00[c], qmax) * w00
                  + qlevel(t01[c], qmax) * w01
                  + qlevel(t10[c], qmax) * w10
                  + qlevel(t11[c], qmax) * w11;
        res[c] = acc * invq;
    }
}

__global__ void __launch_bounds__(BLK)
gather_kernel(const float* __restrict__ hi,
              const float* __restrict__ lo,
              float* __restrict__ out) {
    int t = blockIdx.x * BLK + threadIdx.x;
    int s = t >> 2;       // sorted position
    int j = t & 3;        // output float4 group

    float4 rec = __ldg(reinterpret_cast<const float4*>(g_sorted) + s);
    int idx = __float_as_int(rec.z);

    float res[4];
    if (j < 3) {
        const size_t plane = (size_t)2048 * 2048;
        sample4<2048>(hi + (size_t)(j * 4) * plane, rec.x, rec.y,
                      255.0f, 1.0f / 255.0f, res);
    } else {
        sample4<512>(lo, rec.x, rec.y, 15.0f, 1.0f / 15.0f, res);
    }

    reinterpret_cast<float4*>(out)[(size_t)idx * 4 + j] =
        make_float4(res[0], res[1], res[2], res[3]);
}

// ---------------------------------------------------------------- launch
extern "C" void kernel_launch(void* const* d_in, const int* in_sizes, int n_in,
                              void* d_out, int out_size) {
    const float* uv = (const float*)d_in[0];
    const float* hi = (const float*)d_in[1];
    const float* lo = (const float*)d_in[2];
    float* out = (float*)d_out;

    hist_kernel<<<NSAMP / 4 / BLK, BLK>>>(uv);
    scan_kernel<<<1, SCAN_T>>>();
    scatter_kernel<<<NSAMP / 4 / BLK, BLK>>>(uv);
    gather_kernel<<<NSAMP * 4 / BLK, BLK>>>(hi, lo, out);
}

// round 11
// speedup vs baseline: 1.0381x; 1.0381x over previous
#include <cuda_runtime.h>
#include <cstdint>

// LatentTexture: quantize-then-bilinear-sample two latent textures.
//   hi: 12 ch, 2048x2048, 8-bit quant (qmax=255)
//   lo:  4 ch,  512x512,  4-bit quant (qmax=15)
// out[b,0:12]=hi, out[b,12:16]=lo. fp32.
//
// R11:
//  - ONE fused sort kernel (hist + 16-block scan + scatter) with resident-grid
//    spin barriers; sample keys live in registers across phases.
//  - Gather: Morton-sorted samples AND channel-group phasing (slow grid axis)
//    for DRAM row-buffer locality on the irreducible ~190MB of granule misses.

#define NSAMP 131072
#define BLK 256
#define NBINS 16384            // 128x128 tiles of 16x16 hi texels
#define SORT_BLOCKS 512        // NSAMP / BLK, all co-resident in wave 1
#define SCAN_BLOCKS 16         // blocks participating in the scan phase

__device__ int    g_hist[NBINS];      // zeroed at load; scan re-zeroes
__device__ int    g_cursor[NBINS];
__device__ int    g_chunk_sum[SCAN_BLOCKS];
__device__ int    g_done_hist;        // arrival counters (reset by last block)
__device__ int    g_done_part;
__device__ int    g_done_scan;
__device__ int    g_done_all;
__device__ float4 g_sorted[NSAMP];    // (u, v, idx_bits, pad)

// ---------------------------------------------------------------- helpers
__device__ __forceinline__ float qlevel(float x, float qmax) {
    float xc = fminf(fmaxf(x, 0.0f), 1.0f);
    return rintf(__fmul_rn(xc, qmax));
}

__device__ __forceinline__ uint32_t spread8(uint32_t x) {
    x &= 0xFFu;
    x = (x | (x << 4)) & 0x0F0Fu;
    x = (x | (x << 2)) & 0x3333u;
    x = (x | (x << 1)) & 0x5555u;
    return x;
}

__device__ __forceinline__ int sample_key(float u, float v) {
    float gx = __fadd_rn(__fmul_rn(u, 2.0f), -1.0f);
    float gy = __fadd_rn(__fmul_rn(v, 2.0f), -1.0f);
    float ix = __fmul_rn(__fmul_rn(__fadd_rn(gx, 1.0f), 0.5f), 2047.0f);
    float iy = __fmul_rn(__fmul_rn(__fadd_rn(gy, 1.0f), 0.5f), 2047.0f);
    int tx = min(max((int)floorf(ix), 0), 2047) >> 4;   // 0..127
    int ty = min(max((int)floorf(iy), 0), 2047) >> 4;   // 0..127
    return (int)((spread8((uint32_t)ty) << 1) | spread8((uint32_t)tx));
}

__device__ __forceinline__ void spin_until(int* ctr, int target) {
    volatile int* vp = (volatile int*)ctr;
    while (*vp < target) __nanosleep(64);
}

// ---------------------------------------------------------------- fused sort
__global__ void __launch_bounds__(BLK)
sort_fused_kernel(const float* __restrict__ uv) {
    int b = blockIdx.x;
    int tid = threadIdx.x;
    int i = b * BLK + tid;                 // exactly one sample per thread

    // ---- phase 1: histogram (keys stay in registers) ----
    float2 p = __ldg(reinterpret_cast<const float2*>(uv) + i);
    int key = sample_key(p.x, p.y);
    atomicAdd(&g_hist[key], 1);            // result unused -> RED

    __syncthreads();
    if (tid == 0) {
        __threadfence();
        atomicAdd(&g_done_hist, 1);
    }

    // ---- phase 2: scan (blocks 0..15), 1024 bins each, 4 bins/thread ----
    __shared__ int sh_bcast;
    __shared__ int sh_wsum[8];
    __shared__ int sh_btot;
    if (b < SCAN_BLOCKS) {
        if (tid == 0) spin_until(&g_done_hist, SORT_BLOCKS);
        __syncthreads();
        __threadfence();

        int4 v = reinterpret_cast<const int4*>(g_hist)[b * BLK + tid];
        int s = v.x + v.y + v.z + v.w;

        int lane = tid & 31;
        int w = tid >> 5;
        int inc = s;
#pragma unroll
        for (int d = 1; d < 32; d <<= 1) {
            int t = __shfl_up_sync(0xffffffffu, inc, d);
            if (lane >= d) inc += t;
        }
        if (lane == 31) sh_wsum[w] = inc;
        __syncthreads();
        if (w == 0 && lane < 8) {
            int x = sh_wsum[lane];
            int wi = x;
#pragma unroll
            for (int d = 1; d < 8; d <<= 1) {
                int t = __shfl_up_sync(0xffu, wi, d);
                if (lane >= d) wi += t;
            }
            sh_wsum[lane] = wi - x;        // exclusive warp offsets
            if (lane == 7) sh_btot = wi;   // block total
        }
        __syncthreads();

        if (tid == 0) {
            g_chunk_sum[b] = sh_btot;
            __threadfence();
            atomicAdd(&g_done_part, 1);
            spin_until(&g_done_part, SCAN_BLOCKS);
            __threadfence();
            int off = 0;
            for (int k = 0; k < b; ++k) off += g_chunk_sum[k];
            sh_bcast = off;
        }
        __syncthreads();

        int run = sh_bcast + sh_wsum[w] + inc - s;   // exclusive global offset
        int4 c;
        c.x = run;  run += v.x;
        c.y = run;  run += v.y;
        c.z = run;  run += v.z;
        c.w = run;
        reinterpret_cast<int4*>(g_cursor)[b * BLK + tid] = c;
        // re-zero hist for the next graph replay
        reinterpret_cast<int4*>(g_hist)[b * BLK + tid] = make_int4(0, 0, 0, 0);

        __syncthreads();
        if (tid == 0) {
            __threadfence();
            atomicAdd(&g_done_scan, 1);
        }
    }

    // ---- phase 3: scatter ----
    if (tid == 0) spin_until(&g_done_scan, SCAN_BLOCKS);
    __syncthreads();

    int pos = atomicAdd(&g_cursor[key], 1);
    g_sorted[pos] = make_float4(p.x, p.y, __int_as_float(i), 0.0f);

    // ---- cleanup: last-arriving block resets control vars ----
    if (tid == 0) {
        int d = atomicAdd(&g_done_all, 1);
        if (d == SORT_BLOCKS - 1) {
            g_done_hist = 0;
            g_done_part = 0;
            g_done_scan = 0;
            g_done_all  = 0;
        }
    }
}

// ---------------------------------------------------------------- gather
template <int HW>
__device__ __forceinline__ void sample4(const float* __restrict__ tex,
                                        float u, float v,
                                        float qmax, float invq,
                                        float* __restrict__ res) {
    float gx = __fadd_rn(__fmul_rn(u, 2.0f), -1.0f);
    float gy = __fadd_rn(__fmul_rn(v, 2.0f), -1.0f);
    float ix = __fmul_rn(__fmul_rn(__fadd_rn(gx, 1.0f), 0.5f), (float)(HW - 1));
    float iy = __fmul_rn(__fmul_rn(__fadd_rn(gy, 1.0f), 0.5f), (float)(HW - 1));

    float ix0f = floorf(ix);
    float iy0f = floorf(iy);
    float wx = __fadd_rn(ix, -ix0f);
    float wy = __fadd_rn(iy, -iy0f);

    int ix0 = min(max((int)ix0f, 0), HW - 1);
    int iy0 = min(max((int)iy0f, 0), HW - 1);
    int ix1 = min(ix0 + 1, HW - 1);
    int iy1 = min(iy0 + 1, HW - 1);

    float w00 = (1.0f - wy) * (1.0f - wx);
    float w01 = (1.0f - wy) * wx;
    float w10 = wy * (1.0f - wx);
    float w11 = wy * wx;

    size_t r0 = (size_t)iy0 * HW;
    size_t r1 = (size_t)iy1 * HW;
    size_t o00 = r0 + ix0, o01 = r0 + ix1;
    size_t o10 = r1 + ix0, o11 = r1 + ix1;

    const size_t plane = (size_t)HW * HW;

    float t00[4], t01[4], t10[4], t11[4];
#pragma unroll
    for (int c = 0; c < 4; ++c) {
        const float* p = tex + (size_t)c * plane;
        t00[c] = __ldg(p + o00);
        t01[c] = __ldg(p + o01);
        t10[c] = __ldg(p + o10);
        t11[c] = __ldg(p + o11);
    }
#pragma unroll
    for (int c = 0; c < 4; ++c) {
        float acc = qlevel(t00[c], qmax) * w00
                  + qlevel(t01[c], qmax) * w01
                  + qlevel(t10[c], qmax) * w10
                  + qlevel(t11[c], qmax) * w11;
        res[c] = acc * invq;
    }
}

__global__ void __launch_bounds__(BLK)
gather_kernel(const float* __restrict__ hi,
              const float* __restrict__ lo,
              float* __restrict__ out) {
    int j = blockIdx.x >> 9;                              // channel-group phase
    int s = ((blockIdx.x & 511) << 8) + threadIdx.x;      // sorted position

    float4 rec = __ldg(reinterpret_cast<const float4*>(g_sorted) + s);
    int idx = __float_as_int(rec.z);

    float res[4];
    if (j < 3) {
        const size_t plane = (size_t)2048 * 2048;
        sample4<2048>(hi + (size_t)(j * 4) * plane, rec.x, rec.y,
                      255.0f, 1.0f / 255.0f, res);
    } else {
        sample4<512>(lo, rec.x, rec.y, 15.0f, 1.0f / 15.0f, res);
    }

    reinterpret_cast<float4*>(out)[(size_t)idx * 4 + j] =
        make_float4(res[0], res[1], res[2], res[3]);
}

// ---------------------------------------------------------------- launch
extern "C" void kernel_launch(void* const* d_in, const int* in_sizes, int n_in,
                              void* d_out, int out_size) {
    const float* uv = (const float*)d_in[0];
    const float* hi = (const float*)d_in[1];
    const float* lo = (const float*)d_in[2];
    float* out = (float*)d_out;

    sort_fused_kernel<<<SORT_BLOCKS, BLK>>>(uv);
    gather_kernel<<<4 * SORT_BLOCKS, BLK>>>(hi, lo, out);
}